// round 1
// baseline (speedup 1.0000x reference)
#include <cuda_runtime.h>
#include <cuda_bf16.h>
#include <cstdint>

// ---------------------------------------------------------------------------
// MLGRUCell: y = activation_quant(layernorm(x)); three ternary matmuls with
// sign(W_{f,c,g}); gates; o_t = g*h, h_t = f*h_prev + (1-f)*c.
//
// Exact-integer trick: quantized activations are integers in [-128,127] and
// weights are {-1,0,+1}; both exact in bf16, dot of 128 exact in fp32 accum.
// So mma.sync bf16 computes the ternary matmul exactly.
// ---------------------------------------------------------------------------

// Weight fragments: [mat(3)][ntpair(8)][kt(8)][lane(32)] as uint4
//   .x = b0b1 (n even tile), .y = b2b3 (n even), .z/.w = same for n odd tile
__device__ uint4 g_wfrag[3 * 8 * 8 * 32];

__device__ __forceinline__ unsigned sgn_bf16(float v) {
    // bf16 bit patterns: +1.0 = 0x3F80, -1.0 = 0xBF80, 0.0 = 0x0000
    return v > 0.f ? 0x3F80u : (v < 0.f ? 0xBF80u : 0u);
}

__global__ void prep_kernel(const float* __restrict__ Wf,
                            const float* __restrict__ Wc,
                            const float* __restrict__ Wg) {
    int idx = blockIdx.x * blockDim.x + threadIdx.x;
    if (idx >= 3 * 8 * 8 * 32) return;
    int lane = idx & 31;
    int kt   = (idx >> 5) & 7;
    int ntp  = (idx >> 8) & 7;
    int mat  = idx >> 11;
    const float* W = (mat == 0) ? Wf : ((mat == 1) ? Wc : Wg);
    int g = lane >> 2, tig = lane & 3;
    // B[k][n] = sign(W[n][k]);  W is [hidden=128][in=128] row-major
    int ne = ntp * 16 + g;       // even n-tile column
    int no = ne + 8;             // odd  n-tile column
    int k0 = kt * 16 + tig * 2;
    uint4 r;
    r.x = sgn_bf16(W[ne * 128 + k0])     | (sgn_bf16(W[ne * 128 + k0 + 1]) << 16);
    r.y = sgn_bf16(W[ne * 128 + k0 + 8]) | (sgn_bf16(W[ne * 128 + k0 + 9]) << 16);
    r.z = sgn_bf16(W[no * 128 + k0])     | (sgn_bf16(W[no * 128 + k0 + 1]) << 16);
    r.w = sgn_bf16(W[no * 128 + k0 + 8]) | (sgn_bf16(W[no * 128 + k0 + 9]) << 16);
    g_wfrag[idx] = r;
}

#define MMA_OP(D, A, b0, b1)                                                   \
    asm volatile(                                                              \
        "mma.sync.aligned.m16n8k16.row.col.f32.bf16.bf16.f32 "                 \
        "{%0,%1,%2,%3}, {%4,%5,%6,%7}, {%8,%9}, {%0,%1,%2,%3};\n"              \
        : "+f"(D[0]), "+f"(D[1]), "+f"(D[2]), "+f"(D[3])                       \
        : "r"(A.x), "r"(A.y), "r"(A.z), "r"(A.w), "r"(b0), "r"(b1))

__device__ __forceinline__ float sigmoidf_(float y) {
    return __fdividef(1.f, 1.f + __expf(-y));
}

__global__ __launch_bounds__(128) void mlgru_kernel(
    const float* __restrict__ x, const float* __restrict__ hprev,
    const float* __restrict__ bf_, const float* __restrict__ bc_,
    const float* __restrict__ bg_, float* __restrict__ out, long long half) {
    // qfrag: A fragments, [mtile(8)][ktile(8)][lane(32)] -> uint4 (a0..a3)
    __shared__ uint4 qfrag[8][8][32];
    __shared__ float sinv[128];
    __shared__ float bias_sh[3][128];

    const int tid = threadIdx.x;
    const int w = tid >> 5, l = tid & 31;
    const long long rowBlock = (long long)blockIdx.x * 128;

    bias_sh[0][tid] = bf_[tid];
    bias_sh[1][tid] = bc_[tid];
    bias_sh[2][tid] = bg_[tid];

    // ------------------- Phase 1: layernorm + quant -------------------
    // Each warp iteration handles 4 rows; lane l works on row (l>>3),
    // columns (l&7)*4 + 32j  (j = 0..3).  Segmented shfl_xor over 8 lanes.
    {
        const int clb = (l & 7) * 4;
        #pragma unroll 1
        for (int it = 0; it < 8; it++) {
            const int r = w * 32 + it * 4 + (l >> 3);
            const float4* xr = (const float4*)(x + (rowBlock + r) * 128);
            float4 v[4];
            #pragma unroll
            for (int j = 0; j < 4; j++) v[j] = xr[(clb >> 2) + 8 * j];

            float s1 = 0.f, s2 = 0.f;
            #pragma unroll
            for (int j = 0; j < 4; j++) {
                s1 += v[j].x + v[j].y + v[j].z + v[j].w;
                s2 += v[j].x * v[j].x + v[j].y * v[j].y +
                      v[j].z * v[j].z + v[j].w * v[j].w;
            }
            #pragma unroll
            for (int m = 1; m <= 4; m <<= 1) {
                s1 += __shfl_xor_sync(0xffffffffu, s1, m);
                s2 += __shfl_xor_sync(0xffffffffu, s2, m);
            }
            const float mean = s1 * (1.f / 128.f);
            const float var  = s2 * (1.f / 128.f) - mean * mean;
            const float rstd = 1.f / sqrtf(var + 1e-8f);

            float xn[16];
            float mx = 0.f;
            #pragma unroll
            for (int j = 0; j < 4; j++) {
                xn[4*j+0] = (v[j].x - mean) * rstd;
                xn[4*j+1] = (v[j].y - mean) * rstd;
                xn[4*j+2] = (v[j].z - mean) * rstd;
                xn[4*j+3] = (v[j].w - mean) * rstd;
                mx = fmaxf(mx, fabsf(xn[4*j+0]));
                mx = fmaxf(mx, fabsf(xn[4*j+1]));
                mx = fmaxf(mx, fabsf(xn[4*j+2]));
                mx = fmaxf(mx, fabsf(xn[4*j+3]));
            }
            #pragma unroll
            for (int m = 1; m <= 4; m <<= 1)
                mx = fmaxf(mx, __shfl_xor_sync(0xffffffffu, mx, m));

            const float s  = 127.f / mx;       // quant scale
            const float si = mx / 127.f;       // dequant scale
            if ((l & 7) == 0) sinv[r] = si;

            const int mt = r >> 4, g8 = r & 7, hi2 = (r >> 3) & 1;
            #pragma unroll
            for (int j = 0; j < 4; j++) {
                float q[4];
                #pragma unroll
                for (int e = 0; e < 4; e++)
                    q[e] = fminf(fmaxf(rintf(s * xn[4*j+e]), -128.f), 127.f);
                #pragma unroll
                for (int p = 0; p < 2; p++) {
                    const int c0 = clb + 32 * j + 2 * p;
                    // bf16 of small ints == high 16 bits of the fp32 (exact)
                    unsigned u = (__float_as_uint(q[2*p]) >> 16) |
                                 (__float_as_uint(q[2*p+1]) & 0xFFFF0000u);
                    const int kt  = c0 >> 4;
                    const int tg  = (c0 >> 1) & 3;
                    const int khi = (c0 >> 3) & 1;
                    ((unsigned*)&qfrag[mt][kt][(g8 << 2) | tg])[hi2 | (khi << 1)] = u;
                }
            }
        }
    }
    __syncthreads();

    // ------------------- Phase 2: 3 ternary MMAs + gates -------------------
    const int g = l >> 2, tig = l & 3;
    const uint4* qA = &qfrag[2 * w][0][l];
    const uint4* qB = &qfrag[2 * w + 1][0][l];

    #pragma unroll 1
    for (int chunk = 0; chunk < 8; chunk++) {   // 16 output columns per chunk
        float acc[3][2][2][4];
        #pragma unroll
        for (int m_ = 0; m_ < 3; m_++)
            #pragma unroll
            for (int a_ = 0; a_ < 2; a_++)
                #pragma unroll
                for (int b_ = 0; b_ < 2; b_++)
                    #pragma unroll
                    for (int e_ = 0; e_ < 4; e_++) acc[m_][a_][b_][e_] = 0.f;

        #pragma unroll
        for (int kt = 0; kt < 8; kt++) {
            const uint4 A0 = qA[kt * 32];
            const uint4 A1 = qB[kt * 32];
            #pragma unroll
            for (int mat = 0; mat < 3; mat++) {
                const uint4 Bv = g_wfrag[((mat * 8 + chunk) * 8 + kt) * 32 + l];
                MMA_OP(acc[mat][0][0], A0, Bv.x, Bv.y);
                MMA_OP(acc[mat][1][0], A1, Bv.x, Bv.y);
                MMA_OP(acc[mat][0][1], A0, Bv.z, Bv.w);
                MMA_OP(acc[mat][1][1], A1, Bv.z, Bv.w);
            }
        }

        // Epilogue: dequant, bias, gates, h/o, store float2
        #pragma unroll
        for (int mt = 0; mt < 2; mt++) {
            const int rloc = w * 32 + mt * 16 + g;
            const float si0 = sinv[rloc], si1 = sinv[rloc + 8];
            #pragma unroll
            for (int nt = 0; nt < 2; nt++) {
                const int c = chunk * 16 + nt * 8 + tig * 2;
                const float bF0 = bias_sh[0][c], bF1 = bias_sh[0][c + 1];
                const float bC0 = bias_sh[1][c], bC1 = bias_sh[1][c + 1];
                const float bG0 = bias_sh[2][c], bG1 = bias_sh[2][c + 1];
                #pragma unroll
                for (int rh = 0; rh < 2; rh++) {
                    const float si = rh ? si1 : si0;
                    const long long row = rowBlock + rloc + rh * 8;
                    const float2 hp = *(const float2*)(hprev + row * 128 + c);
                    const int i0 = rh * 2;

                    const float yf0 = acc[0][mt][nt][i0]     * si + bF0;
                    const float yf1 = acc[0][mt][nt][i0 + 1] * si + bF1;
                    const float yc0 = acc[1][mt][nt][i0]     * si + bC0;
                    const float yc1 = acc[1][mt][nt][i0 + 1] * si + bC1;
                    const float yg0 = acc[2][mt][nt][i0]     * si + bG0;
                    const float yg1 = acc[2][mt][nt][i0 + 1] * si + bG1;

                    const float f0 = sigmoidf_(yf0), f1 = sigmoidf_(yf1);
                    const float cv0 = yc0 * sigmoidf_(yc0);
                    const float cv1 = yc1 * sigmoidf_(yc1);
                    const float gg0 = sigmoidf_(yg0), gg1 = sigmoidf_(yg1);

                    const float h0 = f0 * hp.x + (1.f - f0) * cv0;
                    const float h1 = f1 * hp.y + (1.f - f1) * cv1;
                    float2 ov; ov.x = gg0 * h0; ov.y = gg1 * h1;
                    float2 hv; hv.x = h0;       hv.y = h1;

                    *(float2*)(out + row * 128 + c)        = ov;
                    *(float2*)(out + half + row * 128 + c) = hv;
                }
            }
        }
    }
}

extern "C" void kernel_launch(void* const* d_in, const int* in_sizes, int n_in,
                              void* d_out, int out_size) {
    const float* x  = (const float*)d_in[0];
    const float* h  = (const float*)d_in[1];
    const float* Wf = (const float*)d_in[2];
    const float* Wc = (const float*)d_in[3];
    const float* Wg = (const float*)d_in[4];
    const float* bf = (const float*)d_in[5];
    const float* bc = (const float*)d_in[6];
    const float* bg = (const float*)d_in[7];
    float* out = (float*)d_out;

    prep_kernel<<<48, 128>>>(Wf, Wc, Wg);

    const int rows = in_sizes[0] / 128;      // 262144
    const int blocks = rows / 128;           // 2048
    const long long half = (long long)out_size / 2;
    mlgru_kernel<<<blocks, 128>>>(x, h, bf, bc, bg, out, half);
}